// round 5
// baseline (speedup 1.0000x reference)
#include <cuda_runtime.h>
#include <cstdint>

#define DI __device__ __forceinline__

static constexpr int D       = 4096;
static constexpr int ROWS    = 16384;
static constexpr int TILE_M  = 128;
static constexpr int NCTA    = ROWS / TILE_M;    // 128
static constexpr int CK      = 64;               // k-floats per chunk
static constexpr int NCHUNK  = D / CK;           // 64
static constexpr int S       = 4;                // pipeline stages

static constexpr int XROW    = CK + 4;           // 68 floats (padded row)
static constexpr int XROWB   = XROW * 4;         // 272 bytes
static constexpr int XBYTES  = TILE_M * XROWB;   // 34816
static constexpr int WBYTES  = 24 * XROWB;       // 6528
static constexpr int STG     = XBYTES + WBYTES;  // 41344 per stage
static constexpr int WOFF    = XBYTES;
static constexpr int SM_DOTS = S * STG;          // 165376
static constexpr int DSTRIDE = 25;               // dots row stride (24 dots + ssq)
static constexpr int SM_TOTAL = SM_DOTS + TILE_M * DSTRIDE * 4;  // 178176

static constexpr int W4      = 24 * XROW / 4;    // 408 float4 per W chunk

// g-folded, zero-padded weight image, chunk-grouped: [NCHUNK][24][XROW]
__device__ __align__(16) float g_Wsw[NCHUNK * 24 * XROW];

// ---------------------------------------------------------------------------
DI uint32_t smem_u32(const void* p) {
    uint32_t a;
    asm("{ .reg .u64 t; cvta.to.shared.u64 t, %1; cvt.u32.u64 %0, t; }" : "=r"(a) : "l"(p));
    return a;
}
DI void cp16(uint32_t dst, const void* src) {
    asm volatile("cp.async.cg.shared.global [%0], [%1], 16;" :: "r"(dst), "l"(src) : "memory");
}
#define CP_COMMIT() asm volatile("cp.async.commit_group;" ::: "memory")
#define CP_WAIT3()  asm volatile("cp.async.wait_group 3;" ::: "memory")

DI float lds32(uint32_t addr) {
    float v;
    asm volatile("ld.shared.f32 %0, [%1];" : "=f"(v) : "r"(addr));
    return v;
}
DI void mma_tf32(float& d0, float& d1, float& d2, float& d3,
                 float a0, float a1, float a2, float a3, float b0, float b1) {
    asm volatile(
        "mma.sync.aligned.m16n8k8.row.col.f32.tf32.tf32.f32 "
        "{%0,%1,%2,%3}, {%4,%5,%6,%7}, {%8,%9}, {%0,%1,%2,%3};"
        : "+f"(d0), "+f"(d1), "+f"(d2), "+f"(d3)
        : "r"(__float_as_uint(a0)), "r"(__float_as_uint(a1)),
          "r"(__float_as_uint(a2)), "r"(__float_as_uint(a3)),
          "r"(__float_as_uint(b0)), "r"(__float_as_uint(b1)));
}
DI float sigmoidf_(float x) { return 1.0f / (1.0f + __expf(-x)); }

// ---------------------------------------------------------------------------
// Prep: W_cat (pre|post|res) * g, zero-padded rows of XROW, chunk-grouped so
// the mainloop W copy is a flat float4 memcpy.
// ---------------------------------------------------------------------------
__global__ void prep_w(const float* __restrict__ Wpre, const float* __restrict__ Wpost,
                       const float* __restrict__ Wres, const float* __restrict__ g) {
    for (int idx = blockIdx.x * blockDim.x + threadIdx.x;
         idx < NCHUNK * 24 * XROW; idx += gridDim.x * blockDim.x) {
        int c   = idx / (24 * XROW);
        int rem = idx % (24 * XROW);
        int j   = rem / XROW;
        int k   = rem % XROW;
        float v = 0.0f;
        if (k < CK) {
            int kk = c * CK + k;
            float w = (j < 4)  ? Wpre[j * D + kk]
                    : (j < 8)  ? Wpost[(j - 4) * D + kk]
                    :            Wres[(j - 8) * D + kk];
            v = w * g[kk];
        }
        g_Wsw[idx] = v;
    }
}

// ---------------------------------------------------------------------------
// Main fused kernel: one CTA per 128-row tile.
// Warp w owns rows [16w, 16w+16); computes 24 dots via 3 m16n8k8 tf32 tiles,
// sum-of-squares folded from the A fragments (no extra SMEM traffic).
// ---------------------------------------------------------------------------
__global__ void __launch_bounds__(256, 1)
mhc_main(const float* __restrict__ X,
         const float* __restrict__ b_pre, const float* __restrict__ b_post,
         const float* __restrict__ b_res,
         const float* __restrict__ alpha_pre, const float* __restrict__ alpha_post,
         const float* __restrict__ alpha_res,
         float* __restrict__ out) {
    extern __shared__ char smem[];
    float* sm = reinterpret_cast<float*>(smem);
    const uint32_t sb = smem_u32(smem);
    const int tid  = threadIdx.x;
    const int wid  = tid >> 5, lane = tid & 31;
    const int gq   = lane >> 2, cq = lane & 3;   // quad row-group / col
    const int wr   = wid * 16;                   // warp row base in tile
    const long row0 = (long)blockIdx.x * TILE_M;
    const float* xtile = X + row0 * D;

    // ---- stage-issue helper ----
    // X: 2048 float4 per stage, 8 per thread; W: 408 float4.
    const int xr = tid >> 4, xq = tid & 15;      // fixed per-thread X mapping base
    auto issue_stage = [&](int st, int c) {
        uint32_t xb = sb + st * STG;
        const float* xs = xtile + c * CK;
        #pragma unroll
        for (int i = 0; i < 8; i++) {
            int r = xr + i * 16;
            cp16(xb + r * XROWB + xq * 16, xs + (long)r * D + xq * 4);
        }
        const float4* wsrc = reinterpret_cast<const float4*>(g_Wsw + c * 24 * XROW);
        if (tid < W4)       cp16(xb + WOFF + tid * 16, wsrc + tid);
        if (tid + 256 < W4) cp16(xb + WOFF + (tid + 256) * 16, wsrc + tid + 256);
    };

    // ---- prologue ----
    #pragma unroll
    for (int s = 0; s < S; s++) { issue_stage(s, s); CP_COMMIT(); }

    float acc[3][4];
    #pragma unroll
    for (int n = 0; n < 3; n++)
        #pragma unroll
        for (int i = 0; i < 4; i++) acc[n][i] = 0.0f;
    float ss0 = 0.0f, ss1 = 0.0f;

    // ---- mainloop ----
    for (int c = 0; c < NCHUNK; c++) {
        const int st = c & (S - 1);
        CP_WAIT3();
        __syncthreads();

        const uint32_t xbase = sb + st * STG;
        const uint32_t abase = xbase + (wr + gq) * XROWB + cq * 4;
        const uint32_t bbase = xbase + WOFF + gq * XROWB + cq * 4;

        #pragma unroll
        for (int k0 = 0; k0 < 8; k0++) {
            const uint32_t ka = abase + k0 * 32;
            float a0 = lds32(ka);
            float a1 = lds32(ka + 8 * XROWB);
            float a2 = lds32(ka + 16);
            float a3 = lds32(ka + 8 * XROWB + 16);
            ss0 = fmaf(a0, a0, ss0); ss0 = fmaf(a2, a2, ss0);
            ss1 = fmaf(a1, a1, ss1); ss1 = fmaf(a3, a3, ss1);
            const uint32_t kb = bbase + k0 * 32;
            #pragma unroll
            for (int n = 0; n < 3; n++) {
                float b0 = lds32(kb + n * 8 * XROWB);
                float b1 = lds32(kb + n * 8 * XROWB + 16);
                mma_tf32(acc[n][0], acc[n][1], acc[n][2], acc[n][3],
                         a0, a1, a2, a3, b0, b1);
            }
        }
        __syncthreads();
        const int nc = c + S;
        if (nc < NCHUNK) issue_stage(st, nc);
        CP_COMMIT();
    }

    // ---- dump fragments + sumsq to SMEM ----
    float* dots = sm + SM_DOTS / 4;
    #pragma unroll
    for (int n = 0; n < 3; n++) {
        int col = n * 8 + 2 * cq;
        dots[(wr + gq) * DSTRIDE + col]         = acc[n][0];
        dots[(wr + gq) * DSTRIDE + col + 1]     = acc[n][1];
        dots[(wr + gq + 8) * DSTRIDE + col]     = acc[n][2];
        dots[(wr + gq + 8) * DSTRIDE + col + 1] = acc[n][3];
    }
    ss0 += __shfl_xor_sync(0xFFFFFFFFu, ss0, 1);
    ss0 += __shfl_xor_sync(0xFFFFFFFFu, ss0, 2);
    ss1 += __shfl_xor_sync(0xFFFFFFFFu, ss1, 1);
    ss1 += __shfl_xor_sync(0xFFFFFFFFu, ss1, 2);
    if (cq == 0) {
        dots[(wr + gq) * DSTRIDE + 24]     = ss0;
        dots[(wr + gq + 8) * DSTRIDE + 24] = ss1;
    }
    __syncthreads();

    // ---- epilogue: one thread per row ----
    if (tid < TILE_M) {
        const float* dr = dots + tid * DSTRIDE;
        const long row = row0 + tid;
        const float ssq  = dr[24];
        const float rstd = rsqrtf(ssq * (1.0f / (float)D) + 1e-6f);
        const float ap  = __ldg(alpha_pre)  * rstd;
        const float aps = __ldg(alpha_post) * rstd;
        const float ar  = __ldg(alpha_res)  * rstd;

        float4 hp;
        hp.x = sigmoidf_(fmaf(ap, dr[0], __ldg(b_pre + 0)));
        hp.y = sigmoidf_(fmaf(ap, dr[1], __ldg(b_pre + 1)));
        hp.z = sigmoidf_(fmaf(ap, dr[2], __ldg(b_pre + 2)));
        hp.w = sigmoidf_(fmaf(ap, dr[3], __ldg(b_pre + 3)));
        reinterpret_cast<float4*>(out)[row] = hp;

        float4 ho;
        ho.x = 2.0f * sigmoidf_(fmaf(aps, dr[4], __ldg(b_post + 0)));
        ho.y = 2.0f * sigmoidf_(fmaf(aps, dr[5], __ldg(b_post + 1)));
        ho.z = 2.0f * sigmoidf_(fmaf(aps, dr[6], __ldg(b_post + 2)));
        ho.w = 2.0f * sigmoidf_(fmaf(aps, dr[7], __ldg(b_post + 3)));
        reinterpret_cast<float4*>(out)[ROWS + row] = ho;

        float P[16];
        #pragma unroll
        for (int m = 0; m < 16; m++) {
            float h = fmaf(ar, dr[8 + m], __ldg(b_res + m));
            h = fminf(fmaxf(h, -15.0f), 15.0f);
            P[m] = __expf(h);
        }
        #pragma unroll 1
        for (int it = 0; it < 20; it++) {
            #pragma unroll
            for (int j = 0; j < 4; j++) {          // column normalize (axis=-2)
                float s = P[j] + P[4 + j] + P[8 + j] + P[12 + j];
                float inv = __fdividef(1.0f, s + 1e-6f);
                P[j] *= inv; P[4 + j] *= inv; P[8 + j] *= inv; P[12 + j] *= inv;
            }
            #pragma unroll
            for (int i = 0; i < 4; i++) {          // row normalize (axis=-1)
                float s = P[i * 4] + P[i * 4 + 1] + P[i * 4 + 2] + P[i * 4 + 3];
                float inv = __fdividef(1.0f, s + 1e-6f);
                P[i * 4] *= inv; P[i * 4 + 1] *= inv; P[i * 4 + 2] *= inv; P[i * 4 + 3] *= inv;
            }
        }
        float4* ores = reinterpret_cast<float4*>(out) + 2 * ROWS + row * 4;
        ores[0] = make_float4(P[0],  P[1],  P[2],  P[3]);
        ores[1] = make_float4(P[4],  P[5],  P[6],  P[7]);
        ores[2] = make_float4(P[8],  P[9],  P[10], P[11]);
        ores[3] = make_float4(P[12], P[13], P[14], P[15]);
    }
}

// ---------------------------------------------------------------------------
extern "C" void kernel_launch(void* const* d_in, const int* in_sizes, int n_in,
                              void* d_out, int out_size) {
    const float* X      = (const float*)d_in[0];
    const float* g      = (const float*)d_in[1];
    const float* W_pre  = (const float*)d_in[2];
    const float* W_post = (const float*)d_in[3];
    const float* W_res  = (const float*)d_in[4];
    const float* b_pre  = (const float*)d_in[5];
    const float* b_post = (const float*)d_in[6];
    const float* b_res  = (const float*)d_in[7];
    const float* a_pre  = (const float*)d_in[8];
    const float* a_post = (const float*)d_in[9];
    const float* a_res  = (const float*)d_in[10];
    float* out = (float*)d_out;

    cudaFuncSetAttribute(mhc_main, cudaFuncAttributeMaxDynamicSharedMemorySize, SM_TOTAL);

    prep_w<<<(NCHUNK * 24 * XROW + 255) / 256, 256>>>(W_pre, W_post, W_res, g);
    mhc_main<<<NCTA, 256, SM_TOTAL>>>(X, b_pre, b_post, b_res,
                                      a_pre, a_post, a_res, out);
}